// round 7
// baseline (speedup 1.0000x reference)
#include <cuda_runtime.h>
#include <cuda_fp16.h>
#include <math.h>

#define HH 512
#define WW 512
#define AA 180
#define TST 516             // pair-image row stride in half2 (2064 B/row)
#define CH 16               // padded top-rows per chunk
#define NCHUNK 33           // ceil(513 / 16)
#define NSPLIT 10           // chunk-groups per angle
#define NITEMS (AA * NSPLIT)
#define NBLOCKS 444         // 148 SMs x 3 resident blocks
#define TILE_H2 (CH * TST)  // 8256 half2 = 33,024 B per buffer
#define DYN_SMEM (2 * TILE_H2 * 4)   // 66,048 B

// Vertical-pair images: g_V[y*TST+s] = half2(P(y,s-1), P(y+1,s-1)),
// P(r,c) = pred[r-1][c-1] inside [1,512]^2 else 0. y in [0,513), s in [0,516).
// Columns s=0,1,514,515 are (0,0) guard columns by construction.
__device__ __align__(16) __half2 g_V[513 * TST];
__device__ __align__(16) __half2 g_VT[513 * TST];   // transposed orientation
__device__ __align__(16) float g_sino[AA * WW];
__device__ double g_acc[2];
__device__ unsigned g_cnt;
__device__ unsigned g_work;

// ---------------- cp.async helpers ----------------
__device__ __forceinline__ void cp_async16(void* smem, const void* gmem) {
    unsigned s = (unsigned)__cvta_generic_to_shared(smem);
    asm volatile("cp.async.cg.shared.global [%0], [%1], 16;\n" :: "r"(s), "l"(gmem));
}
__device__ __forceinline__ void cp_commit() {
    asm volatile("cp.async.commit_group;\n");
}
template <int N> __device__ __forceinline__ void cp_wait() {
    asm volatile("cp.async.wait_group %0;\n" :: "n"(N));
}

// ---------------------------------------------------------------------------
// Kernel 1a: normal vertical-pair image (coalesced) + zero accumulators/counters.
// ---------------------------------------------------------------------------
__global__ void prep_normal(const float* __restrict__ pred) {
    const int y = blockIdx.x;          // 0..512
    const int s = threadIdx.x;         // 0..543
    if (s < TST) {
        float a = 0.0f, b = 0.0f;
        if (s >= 2 && s <= 513) {
            const int pc = s - 2;                       // pred col
            if (y >= 1 && y <= 512) a = pred[(y - 1) * 512 + pc];
            if (y <= 511)           b = pred[y * 512 + pc];
        }
        g_V[y * TST + s] = __floats2half2_rn(a, b);
    }
    const int gid = blockIdx.x * blockDim.x + threadIdx.x;
    if (gid < AA * WW) g_sino[gid] = 0.0f;
    if (gid == 0) { g_acc[0] = 0.0; g_acc[1] = 0.0; g_cnt = 0u; g_work = 0u; }
}

// ---------------------------------------------------------------------------
// Kernel 1b: transposed vertical-pair image via SMEM tile.
// g_VT[y][s] = half2(pred[s-2][y-1], pred[s-2][y]) (guarded zeros).
// ---------------------------------------------------------------------------
__global__ void prep_transpose(const float* __restrict__ pred) {
    __shared__ float t[32][35];        // t[i][j] = pred[s0-2+i][y0-1+j]
    const int s0 = blockIdx.x * 32;
    const int y0 = blockIdx.y * 32;
    const int tx = threadIdx.x;        // 0..31
    const int ty = threadIdx.y;        // 0..7

    for (int i = ty; i < 32; i += 8) {
        const int pr = s0 - 2 + i;
        {
            const int pc = y0 - 1 + tx;
            t[i][tx] = ((unsigned)pr < 512u && (unsigned)pc < 512u)
                       ? pred[pr * 512 + pc] : 0.0f;
        }
        if (tx < 2) {
            const int pc = y0 + 31 + tx;
            t[i][32 + tx] = ((unsigned)pr < 512u && (unsigned)pc < 512u)
                            ? pred[pr * 512 + pc] : 0.0f;
        }
    }
    __syncthreads();

    for (int j = ty; j < 32; j += 8) {
        const int y = y0 + j;
        const int s = s0 + tx;
        if (y < 513 && s < TST)
            g_VT[y * TST + s] = __floats2half2_rn(t[tx][j], t[tx][j + 1]);
    }
}

// ---------------------------------------------------------------------------
// Kernel 2: persistent work-stealing radon. 444 resident blocks pop items
// (angle, chunk-group) from g_work; body identical to R6 (half2 pairs,
// cp.async double buffer).
// ---------------------------------------------------------------------------
__global__ __launch_bounds__(512, 3) void radon_kernel(const float* __restrict__ angles) {
    extern __shared__ __align__(16) unsigned char dynsmem[];
    __half2* const tbuf0 = (__half2*)dynsmem;
    __half2* const tbuf1 = tbuf0 + TILE_H2;
    __shared__ unsigned s_item;

    const int w = threadIdx.x;

    for (;;) {
        if (w == 0) s_item = atomicAdd(&g_work, 1u);
        __syncthreads();
        const unsigned item = s_item;
        if (item >= NITEMS) break;

        const int a   = (int)(item / NSPLIT);
        const int grp = (int)(item - (unsigned)a * NSPLIT);

        const float ang = angles[a];
        const float sn = sinf(ang);
        const float cs = cosf(ang);
        const bool  swp = fabsf(sn) > fabsf(cs);

        const float c = swp ? -sn : cs;                // |c| >= 0.7071
        const float d = swp ?  cs : -sn;
        const float u = (float)w + 0.5f - 256.0f;
        const float by = fmaf(swp ? cs : sn, u, 255.5f);
        const float bx = fmaf(swp ? sn : cs, u, 255.5f);
        const __half2* __restrict__ img = swp ? g_VT : g_V;

        const float sgn   = (c >= 0.0f) ? 1.0f : -1.0f;
        const float cy    = fabsf(c);
        const float invcy = 1.0f / cy;
        const float iyS   = fmaf(-255.5f, cy, by);
        const float dxj   = sgn * d;
        const float ixS   = fmaf(-sgn * 255.5f, d, bx);

        const int c0 = (NCHUNK * grp) / NSPLIT;
        const int c1 = (NCHUNK * (grp + 1)) / NSPLIT;

        auto stage = [&](int m, __half2* dstbuf) {
            const int R  = m * CH;
            const int nr = min(R + CH, 513) - R;
            const int n16 = nr * (TST / 4);
            const float4* __restrict__ src = (const float4*)(img + R * TST);
            float4* dst = (float4*)dstbuf;
            for (int t = threadIdx.x; t < n16; t += 512)
                cp_async16(&dst[t], &src[t]);
            cp_commit();
        };

        stage(c0, (c0 & 1) ? tbuf1 : tbuf0);

        float acc = 0.0f;

        for (int m = c0; m < c1; m++) {
            if (m + 1 < c1) {
                stage(m + 1, ((m + 1) & 1) ? tbuf1 : tbuf0);
                cp_wait<1>();
            } else {
                cp_wait<0>();
            }
            __syncthreads();

            const int R  = m * CH;
            const int nr = min(R + CH, 513) - R;

            const int jA0   = (int)ceilf(((float)(R - 1) - iyS) * invcy) - 1;
            const int trips = (int)((float)nr * invcy) + 3;
            const int jA    = min(max(jA0, 0), 512 - trips);

            float iy_loc = fmaf((float)jA, cy,  iyS) - (float)(R - 1);
            float ix_loc = fmaf((float)jA, dxj, ixS) + 2.0f;

            const __half2* __restrict__ tb = (m & 1) ? tbuf1 : tbuf0;

            #pragma unroll 4
            for (int k = 0; k < trips; k++) {
                const int yi = __float2int_rd(iy_loc);
                if ((unsigned)yi < (unsigned)nr) {
                    const float wy = iy_loc - (float)yi;
                    const int   si0 = __float2int_rd(ix_loc);
                    const float wx  = ix_loc - (float)si0;
                    const int   si  = min(max(si0, 0), 514);
                    const __half2 wx2 = __float2half2_rn(wx);
                    const __half2* p = tb + yi * TST + si;
                    const __half2 A = p[0];            // (v00, v10)
                    const __half2 B = p[1];            // (v01, v11)
                    const __half2 mm = __hfma2(wx2, __hsub2(B, A), A);
                    const float top = __low2float(mm);
                    const float bot = __high2float(mm);
                    acc += fmaf(wy, bot - top, top);
                }
                iy_loc += cy;
                ix_loc += dxj;
            }
            __syncthreads();
        }
        atomicAdd(&g_sino[a * WW + w], acc);
        __syncthreads();    // protect s_item before next pop
    }
}

// ---------------------------------------------------------------------------
// Kernel 3: fused MSE + TV reduction (float4 quads) + finalize via counter.
// ---------------------------------------------------------------------------
__global__ void loss_kernel(const float* __restrict__ pred,
                            const float* __restrict__ sino_tgt,
                            float* __restrict__ out) {
    const int tid    = blockIdx.x * blockDim.x + threadIdx.x;
    const int stride = gridDim.x * blockDim.x;

    // MSE over sinogram (float4)
    float lp = 0.0f;
    {
        const float4* __restrict__ s4 = (const float4*)g_sino;
        const float4* __restrict__ t4 = (const float4*)sino_tgt;
        const int n4 = (AA * WW) / 4;                  // 23040
        for (int i = tid; i < n4; i += stride) {
            const float4 s = s4[i];
            const float4 t = t4[i];
            float d0 = s.x - t.x, d1 = s.y - t.y, d2 = s.z - t.z, d3 = s.w - t.w;
            lp = fmaf(d0, d0, lp); lp = fmaf(d1, d1, lp);
            lp = fmaf(d2, d2, lp); lp = fmaf(d3, d3, lp);
        }
    }

    // TV: 511 rows x 128 float4 groups; group at x=508 covers 3 cols.
    float lt = 0.0f;
    {
        const int nitems = 511 * 128;
        for (int it = tid; it < nitems; it += stride) {
            const int y = it >> 7;
            const int x = (it & 127) << 2;
            const float4 p = *(const float4*)(pred + y * 512 + x);
            const float4 q = *(const float4*)(pred + (y + 1) * 512 + x);
            const float dy0 = q.x - p.x, dy1 = q.y - p.y;
            const float dy2 = q.z - p.z, dy3 = q.w - p.w;
            const float dx0 = p.y - p.x, dx1 = p.z - p.y, dx2 = p.w - p.z;
            lt += sqrtf(fmaf(dx0, dx0, fmaf(dy0, dy0, 1e-8f)));
            lt += sqrtf(fmaf(dx1, dx1, fmaf(dy1, dy1, 1e-8f)));
            lt += sqrtf(fmaf(dx2, dx2, fmaf(dy2, dy2, 1e-8f)));
            if (x < 508) {
                const float p4  = pred[y * 512 + x + 4];
                const float dx3 = p4 - p.w;
                lt += sqrtf(fmaf(dx3, dx3, fmaf(dy3, dy3, 1e-8f)));
            }
        }
    }

    for (int off = 16; off > 0; off >>= 1) {
        lp += __shfl_down_sync(0xFFFFFFFFu, lp, off);
        lt += __shfl_down_sync(0xFFFFFFFFu, lt, off);
    }
    __shared__ float s_lp[32], s_lt[32];
    const int lane = threadIdx.x & 31;
    const int warp = threadIdx.x >> 5;
    if (lane == 0) { s_lp[warp] = lp; s_lt[warp] = lt; }
    __syncthreads();
    const int nwarps = blockDim.x >> 5;
    if (warp == 0) {
        lp = (lane < nwarps) ? s_lp[lane] : 0.0f;
        lt = (lane < nwarps) ? s_lt[lane] : 0.0f;
        for (int off = 16; off > 0; off >>= 1) {
            lp += __shfl_down_sync(0xFFFFFFFFu, lp, off);
            lt += __shfl_down_sync(0xFFFFFFFFu, lt, off);
        }
        if (lane == 0) {
            atomicAdd(&g_acc[0], (double)lp);
            atomicAdd(&g_acc[1], (double)lt);
            __threadfence();
            const unsigned done = atomicAdd(&g_cnt, 1u);
            if (done == gridDim.x - 1) {
                __threadfence();
                const double loss_proj = g_acc[0] / (double)(AA * WW);
                const double loss_tv   = g_acc[1] / (double)((HH - 1) * (WW - 1));
                out[0] = (float)(loss_proj + 0.01 * loss_tv);
            }
        }
    }
}

// ---------------------------------------------------------------------------
extern "C" void kernel_launch(void* const* d_in, const int* in_sizes, int n_in,
                              void* d_out, int out_size) {
    const float* pred     = (const float*)d_in[0];   // [1,512,512]
    const float* sinogram = (const float*)d_in[1];   // [1,180,512]
    const float* angles   = (const float*)d_in[2];   // [180]
    float* out = (float*)d_out;

    cudaFuncSetAttribute(radon_kernel,
                         cudaFuncAttributeMaxDynamicSharedMemorySize, DYN_SMEM);

    prep_normal<<<513, 544>>>(pred);

    dim3 tgrid(17, 17);
    prep_transpose<<<tgrid, dim3(32, 8)>>>(pred);

    radon_kernel<<<NBLOCKS, 512, DYN_SMEM>>>(angles);

    loss_kernel<<<148, 256>>>(pred, sinogram, out);
}

// round 8
// speedup vs baseline: 1.0785x; 1.0785x over previous
#include <cuda_runtime.h>
#include <cuda_fp16.h>
#include <math.h>

#define HH 512
#define WW 512
#define AA 180
#define TST 516             // pair-image row stride in half2 (2064 B/row)
#define CH 16               // padded top-rows per chunk
#define NCHUNK 33           // ceil(513 / 16)
#define NSPLIT 10           // chunk-groups per angle -> 1800 blocks
#define TILE_H2 (CH * TST)  // 8256 half2 = 33,024 B per buffer
#define DYN_SMEM (2 * TILE_H2 * 4)   // 66,048 B

#define NORM_BLKS 513
#define TRANS_BLKS 289      // 17 x 17
#define TV_BLKS 64
#define PREP_BLKS (NORM_BLKS + TRANS_BLKS + TV_BLKS)   // 866
#define LOSS_BLKS 296

// Vertical-pair images: g_V[y*TST+s] = half2(P(y,s-1), P(y+1,s-1)),
// P(r,c) = pred[r-1][c-1] inside [1,512]^2 else 0. Cols s=0,1,514,515 are zero.
__device__ __align__(16) __half2 g_V[513 * TST];
__device__ __align__(16) __half2 g_VT[513 * TST];   // transposed orientation
__device__ __align__(16) float g_sino[AA * WW];
__device__ double g_tvpart[TV_BLKS];
__device__ double g_msepart[LOSS_BLKS];
__device__ unsigned g_cnt;

// ---------------- cp.async helpers ----------------
__device__ __forceinline__ void cp_async16(void* smem, const void* gmem) {
    unsigned s = (unsigned)__cvta_generic_to_shared(smem);
    asm volatile("cp.async.cg.shared.global [%0], [%1], 16;\n" :: "r"(s), "l"(gmem));
}
__device__ __forceinline__ void cp_commit() {
    asm volatile("cp.async.commit_group;\n");
}
template <int N> __device__ __forceinline__ void cp_wait() {
    asm volatile("cp.async.wait_group %0;\n" :: "n"(N));
}

// ---------------------------------------------------------------------------
// Kernel 1 (fused prep): role by blockIdx.x.
//   [0,513):    normal vertical-pair image rows + zero g_sino/g_cnt
//   [513,802):  transposed vertical-pair image tiles
//   [802,866):  TV partial sums -> g_tvpart (deterministic slots, no atomics)
// ---------------------------------------------------------------------------
__global__ __launch_bounds__(544) void prep_kernel(const float* __restrict__ pred) {
    const int role = blockIdx.x;
    const int tid  = threadIdx.x;

    if (role < NORM_BLKS) {
        const int y = role;            // 0..512
        if (tid < TST) {
            float a = 0.0f, b = 0.0f;
            if (tid >= 2 && tid <= 513) {
                const int pc = tid - 2;
                if (y >= 1 && y <= 512) a = pred[(y - 1) * 512 + pc];
                if (y <= 511)           b = pred[y * 512 + pc];
            }
            g_V[y * TST + tid] = __floats2half2_rn(a, b);
        }
        const int gid = role * 544 + tid;
        if (gid < AA * WW) g_sino[gid] = 0.0f;
        if (gid == 0) g_cnt = 0u;

    } else if (role < NORM_BLKS + TRANS_BLKS) {
        __shared__ float t[32][35];    // t[i][j] = pred[s0-2+i][y0-1+j]
        const int idx = role - NORM_BLKS;
        const int s0 = (idx % 17) * 32;
        const int y0 = (idx / 17) * 32;
        const int tx = tid & 31;
        const int ty = tid >> 5;       // 0..16

        if (ty < 8) {
            for (int i = ty; i < 32; i += 8) {
                const int pr = s0 - 2 + i;
                {
                    const int pc = y0 - 1 + tx;
                    t[i][tx] = ((unsigned)pr < 512u && (unsigned)pc < 512u)
                               ? pred[pr * 512 + pc] : 0.0f;
                }
                if (tx < 2) {
                    const int pc = y0 + 31 + tx;
                    t[i][32 + tx] = ((unsigned)pr < 512u && (unsigned)pc < 512u)
                                    ? pred[pr * 512 + pc] : 0.0f;
                }
            }
        }
        __syncthreads();
        if (ty < 8) {
            for (int j = ty; j < 32; j += 8) {
                const int y = y0 + j;
                const int s = s0 + tx;
                if (y < 513 && s < TST)
                    g_VT[y * TST + s] = __floats2half2_rn(t[tx][j], t[tx][j + 1]);
            }
        }

    } else {
        // TV partials: 511 rows x 128 float4 groups = 65408 items.
        const int slot = role - NORM_BLKS - TRANS_BLKS;          // 0..63
        const int gtid = slot * 544 + tid;
        const int gstr = TV_BLKS * 544;
        float lt = 0.0f;
        for (int it = gtid; it < 511 * 128; it += gstr) {
            const int y = it >> 7;
            const int x = (it & 127) << 2;
            const float4 p = *(const float4*)(pred + y * 512 + x);
            const float4 q = *(const float4*)(pred + (y + 1) * 512 + x);
            const float dy0 = q.x - p.x, dy1 = q.y - p.y;
            const float dy2 = q.z - p.z, dy3 = q.w - p.w;
            const float dx0 = p.y - p.x, dx1 = p.z - p.y, dx2 = p.w - p.z;
            lt += sqrtf(fmaf(dx0, dx0, fmaf(dy0, dy0, 1e-8f)));
            lt += sqrtf(fmaf(dx1, dx1, fmaf(dy1, dy1, 1e-8f)));
            lt += sqrtf(fmaf(dx2, dx2, fmaf(dy2, dy2, 1e-8f)));
            if (x < 508) {
                const float p4  = pred[y * 512 + x + 4];
                const float dx3 = p4 - p.w;
                lt += sqrtf(fmaf(dx3, dx3, fmaf(dy3, dy3, 1e-8f)));
            }
        }
        for (int off = 16; off > 0; off >>= 1)
            lt += __shfl_down_sync(0xFFFFFFFFu, lt, off);
        __shared__ float s_lt[17];
        if ((tid & 31) == 0) s_lt[tid >> 5] = lt;
        __syncthreads();
        if (tid == 0) {
            float tot = 0.0f;
            for (int i = 0; i < 17; i++) tot += s_lt[i];
            g_tvpart[slot] = (double)tot;
        }
    }
}

// ---------------------------------------------------------------------------
// Kernel 2: radon — exact R6 configuration (grid 180x10, double-buffered).
// ---------------------------------------------------------------------------
__global__ __launch_bounds__(512, 3) void radon_kernel(const float* __restrict__ angles) {
    extern __shared__ __align__(16) unsigned char dynsmem[];
    __half2* const tbuf0 = (__half2*)dynsmem;
    __half2* const tbuf1 = tbuf0 + TILE_H2;

    const int a = blockIdx.x;
    const int w = threadIdx.x;

    const float ang = angles[a];
    const float sn = sinf(ang);
    const float cs = cosf(ang);
    const bool  swp = fabsf(sn) > fabsf(cs);

    const float c = swp ? -sn : cs;                    // |c| >= 0.7071
    const float d = swp ?  cs : -sn;
    const float u = (float)w + 0.5f - 256.0f;
    const float by = fmaf(swp ? cs : sn, u, 255.5f);
    const float bx = fmaf(swp ? sn : cs, u, 255.5f);
    const __half2* __restrict__ img = swp ? g_VT : g_V;

    const float sgn   = (c >= 0.0f) ? 1.0f : -1.0f;
    const float cy    = fabsf(c);
    const float invcy = 1.0f / cy;
    const float iyS   = fmaf(-255.5f, cy, by);
    const float dxj   = sgn * d;
    const float ixS   = fmaf(-sgn * 255.5f, d, bx);

    const int c0 = (NCHUNK * blockIdx.y) / NSPLIT;
    const int c1 = (NCHUNK * (blockIdx.y + 1)) / NSPLIT;

    auto stage = [&](int m, __half2* dstbuf) {
        const int R  = m * CH;
        const int nr = min(R + CH, 513) - R;
        const int n16 = nr * (TST / 4);
        const float4* __restrict__ src = (const float4*)(img + R * TST);
        float4* dst = (float4*)dstbuf;
        for (int t = threadIdx.x; t < n16; t += 512)
            cp_async16(&dst[t], &src[t]);
        cp_commit();
    };

    stage(c0, (c0 & 1) ? tbuf1 : tbuf0);

    float acc = 0.0f;

    for (int m = c0; m < c1; m++) {
        if (m + 1 < c1) {
            stage(m + 1, ((m + 1) & 1) ? tbuf1 : tbuf0);
            cp_wait<1>();
        } else {
            cp_wait<0>();
        }
        __syncthreads();

        const int R  = m * CH;
        const int nr = min(R + CH, 513) - R;

        const int jA0   = (int)ceilf(((float)(R - 1) - iyS) * invcy) - 1;
        const int trips = (int)((float)nr * invcy) + 3;
        const int jA    = min(max(jA0, 0), 512 - trips);

        float iy_loc = fmaf((float)jA, cy,  iyS) - (float)(R - 1);
        float ix_loc = fmaf((float)jA, dxj, ixS) + 2.0f;

        const __half2* __restrict__ tb = (m & 1) ? tbuf1 : tbuf0;

        #pragma unroll 4
        for (int k = 0; k < trips; k++) {
            const int yi = __float2int_rd(iy_loc);
            if ((unsigned)yi < (unsigned)nr) {
                const float wy = iy_loc - (float)yi;
                const int   si0 = __float2int_rd(ix_loc);
                const float wx  = ix_loc - (float)si0;
                const int   si  = min(max(si0, 0), 514);
                const __half2 wx2 = __float2half2_rn(wx);
                const __half2* p = tb + yi * TST + si;
                const __half2 A = p[0];                // (v00, v10)
                const __half2 B = p[1];                // (v01, v11)
                const __half2 mm = __hfma2(wx2, __hsub2(B, A), A);
                const float top = __low2float(mm);
                const float bot = __high2float(mm);
                acc += fmaf(wy, bot - top, top);
            }
            iy_loc += cy;
            ix_loc += dxj;
        }
        __syncthreads();
    }
    atomicAdd(&g_sino[a * WW + w], acc);
}

// ---------------------------------------------------------------------------
// Kernel 3: MSE partials + finalize (last block reduces all partials).
// ---------------------------------------------------------------------------
__global__ __launch_bounds__(256) void loss_kernel(const float* __restrict__ sino_tgt,
                                                   float* __restrict__ out) {
    const int tid    = blockIdx.x * blockDim.x + threadIdx.x;
    const int stride = gridDim.x * blockDim.x;

    float lp = 0.0f;
    {
        const float4* __restrict__ s4 = (const float4*)g_sino;
        const float4* __restrict__ t4 = (const float4*)sino_tgt;
        const int n4 = (AA * WW) / 4;                  // 23040
        for (int i = tid; i < n4; i += stride) {
            const float4 s = s4[i];
            const float4 t = t4[i];
            float d0 = s.x - t.x, d1 = s.y - t.y, d2 = s.z - t.z, d3 = s.w - t.w;
            lp = fmaf(d0, d0, lp); lp = fmaf(d1, d1, lp);
            lp = fmaf(d2, d2, lp); lp = fmaf(d3, d3, lp);
        }
    }

    for (int off = 16; off > 0; off >>= 1)
        lp += __shfl_down_sync(0xFFFFFFFFu, lp, off);
    __shared__ float s_lp[8];
    __shared__ int s_last;
    const int lane = threadIdx.x & 31;
    const int warp = threadIdx.x >> 5;
    if (lane == 0) s_lp[warp] = lp;
    __syncthreads();
    if (threadIdx.x == 0) {
        float tot = 0.0f;
        for (int i = 0; i < 8; i++) tot += s_lp[i];
        g_msepart[blockIdx.x] = (double)tot;
        __threadfence();
        const unsigned done = atomicAdd(&g_cnt, 1u);
        s_last = (done == gridDim.x - 1) ? 1 : 0;
    }
    __syncthreads();

    if (s_last) {
        __threadfence();
        double v = 0.0;
        for (int i = (int)threadIdx.x; i < LOSS_BLKS + TV_BLKS; i += 256)
            v += (i < LOSS_BLKS) ? g_msepart[i] : g_tvpart[i - LOSS_BLKS];
        for (int off = 16; off > 0; off >>= 1)
            v += __shfl_down_sync(0xFFFFFFFFu, v, off);
        __shared__ double s_v[8];
        if (lane == 0) s_v[warp] = v;
        __syncthreads();
        if (threadIdx.x == 0) {
            double tot = 0.0;
            for (int i = 0; i < 8; i++) tot += s_v[i];
            // tot currently mixes: first part MSE, second TV — both summed; need split.
            // (they were summed together; recompute split below)
        }
        __syncthreads();
        if (threadIdx.x == 0) {
            // Reduce separately to apply different normalizations.
            double mse = 0.0, tv = 0.0;
            for (int i = 0; i < LOSS_BLKS; i++) mse += g_msepart[i];
            for (int i = 0; i < TV_BLKS; i++)  tv  += g_tvpart[i];
            const double loss_proj = mse / (double)(AA * WW);
            const double loss_tv   = tv  / (double)((HH - 1) * (WW - 1));
            out[0] = (float)(loss_proj + 0.01 * loss_tv);
        }
    }
}

// ---------------------------------------------------------------------------
extern "C" void kernel_launch(void* const* d_in, const int* in_sizes, int n_in,
                              void* d_out, int out_size) {
    const float* pred     = (const float*)d_in[0];   // [1,512,512]
    const float* sinogram = (const float*)d_in[1];   // [1,180,512]
    const float* angles   = (const float*)d_in[2];   // [180]
    float* out = (float*)d_out;

    cudaFuncSetAttribute(radon_kernel,
                         cudaFuncAttributeMaxDynamicSharedMemorySize, DYN_SMEM);

    prep_kernel<<<PREP_BLKS, 544>>>(pred);

    dim3 rgrid(AA, NSPLIT);                          // 180 x 10 = 1800 blocks
    radon_kernel<<<rgrid, 512, DYN_SMEM>>>(angles);

    loss_kernel<<<LOSS_BLKS, 256>>>(sinogram, out);
}

// round 9
// speedup vs baseline: 1.2054x; 1.1176x over previous
#include <cuda_runtime.h>
#include <cuda_fp16.h>
#include <math.h>

#define HH 512
#define WW 512
#define AA 180
#define TST 516             // pair-image row stride in half2 (2064 B/row)
#define CH 16               // padded top-rows per chunk
#define NCHUNK 33           // ceil(513 / 16)
#define NSPLIT 10           // chunk-groups per angle -> 1800 blocks
#define TILE_H2 (CH * TST)  // 8256 half2 = 33,024 B per buffer
#define DYN_SMEM (2 * TILE_H2 * 4)   // 66,048 B

// Vertical-pair images: g_V[y*TST+s] = half2(P(y,s-1), P(y+1,s-1)),
// P(r,c) = pred[r-1][c-1] inside [1,512]^2 else 0. Cols s=0,1,514,515 are zero.
__device__ __align__(16) __half2 g_V[513 * TST];
__device__ __align__(16) __half2 g_VT[513 * TST];   // transposed orientation
__device__ __align__(16) float g_sino[AA * WW];
__device__ double g_acc[2];
__device__ unsigned g_cnt;

// ---------------- cp.async helpers ----------------
__device__ __forceinline__ void cp_async16(void* smem, const void* gmem) {
    unsigned s = (unsigned)__cvta_generic_to_shared(smem);
    asm volatile("cp.async.cg.shared.global [%0], [%1], 16;\n" :: "r"(s), "l"(gmem));
}
__device__ __forceinline__ void cp_commit() {
    asm volatile("cp.async.commit_group;\n");
}
template <int N> __device__ __forceinline__ void cp_wait() {
    asm volatile("cp.async.wait_group %0;\n" :: "n"(N));
}

// ---------------------------------------------------------------------------
// Kernel 1a: normal vertical-pair image (coalesced) + zero accumulators.
// ---------------------------------------------------------------------------
__global__ void prep_normal(const float* __restrict__ pred) {
    const int y = blockIdx.x;          // 0..512
    const int s = threadIdx.x;         // 0..543
    if (s < TST) {
        float a = 0.0f, b = 0.0f;
        if (s >= 2 && s <= 513) {
            const int pc = s - 2;
            if (y >= 1 && y <= 512) a = pred[(y - 1) * 512 + pc];
            if (y <= 511)           b = pred[y * 512 + pc];
        }
        g_V[y * TST + s] = __floats2half2_rn(a, b);
    }
    const int gid = blockIdx.x * blockDim.x + threadIdx.x;
    if (gid < AA * WW) g_sino[gid] = 0.0f;
    if (gid == 0) { g_acc[0] = 0.0; g_acc[1] = 0.0; g_cnt = 0u; }
}

// ---------------------------------------------------------------------------
// Kernel 1b: transposed vertical-pair image via SMEM tile.
// ---------------------------------------------------------------------------
__global__ void prep_transpose(const float* __restrict__ pred) {
    __shared__ float t[32][35];
    const int s0 = blockIdx.x * 32;
    const int y0 = blockIdx.y * 32;
    const int tx = threadIdx.x;
    const int ty = threadIdx.y;

    for (int i = ty; i < 32; i += 8) {
        const int pr = s0 - 2 + i;
        {
            const int pc = y0 - 1 + tx;
            t[i][tx] = ((unsigned)pr < 512u && (unsigned)pc < 512u)
                       ? pred[pr * 512 + pc] : 0.0f;
        }
        if (tx < 2) {
            const int pc = y0 + 31 + tx;
            t[i][32 + tx] = ((unsigned)pr < 512u && (unsigned)pc < 512u)
                            ? pred[pr * 512 + pc] : 0.0f;
        }
    }
    __syncthreads();

    for (int j = ty; j < 32; j += 8) {
        const int y = y0 + j;
        const int s = s0 + tx;
        if (y < 513 && s < TST)
            g_VT[y * TST + s] = __floats2half2_rn(t[tx][j], t[tx][j + 1]);
    }
}

// ---------------------------------------------------------------------------
// Exact first-j with iy(j) >= bound, iy(j) = fmaf(j, cy, iyS), cy > 0.
// ceilf estimate corrected by +-1 against the same fmaf formula, so any two
// chunks sharing a boundary compute bitwise-identical j -> exact partition.
// ---------------------------------------------------------------------------
__device__ __forceinline__ int first_j_ge(float bound, float iyS, float cy, float invcy) {
    int j = (int)ceilf((bound - iyS) * invcy);
    if (fmaf((float)(j - 1), cy, iyS) >= bound) j -= 1;
    if (fmaf((float)j, cy, iyS) < bound)        j += 1;
    return j;
}

// ---------------------------------------------------------------------------
// Kernel 2: radon with exact guardless j-windows.
// ---------------------------------------------------------------------------
__global__ __launch_bounds__(512, 3) void radon_kernel(const float* __restrict__ angles) {
    extern __shared__ __align__(16) unsigned char dynsmem[];
    __half2* const tbuf0 = (__half2*)dynsmem;
    __half2* const tbuf1 = tbuf0 + TILE_H2;

    const int a = blockIdx.x;
    const int w = threadIdx.x;

    const float ang = angles[a];
    const float sn = sinf(ang);
    const float cs = cosf(ang);
    const bool  swp = fabsf(sn) > fabsf(cs);

    const float c = swp ? -sn : cs;                    // |c| >= 0.7071
    const float d = swp ?  cs : -sn;
    const float u = (float)w + 0.5f - 256.0f;
    const float by = fmaf(swp ? cs : sn, u, 255.5f);
    const float bx = fmaf(swp ? sn : cs, u, 255.5f);
    const __half2* __restrict__ img = swp ? g_VT : g_V;

    const float sgn   = (c >= 0.0f) ? 1.0f : -1.0f;
    const float cy    = fabsf(c);
    const float invcy = 1.0f / cy;
    const float iyS   = fmaf(-255.5f, cy, by);         // iy at j=0, increasing in j
    const float dxj   = sgn * d;
    const float ixS   = fmaf(-sgn * 255.5f, d, bx);

    const int c0 = (NCHUNK * blockIdx.y) / NSPLIT;
    const int c1 = (NCHUNK * (blockIdx.y + 1)) / NSPLIT;

    auto stage = [&](int m, __half2* dstbuf) {
        const int R  = m * CH;
        const int nr = min(R + CH, 513) - R;
        const int n16 = nr * (TST / 4);
        const float4* __restrict__ src = (const float4*)(img + R * TST);
        float4* dst = (float4*)dstbuf;
        for (int t = threadIdx.x; t < n16; t += 512)
            cp_async16(&dst[t], &src[t]);
        cp_commit();
    };

    stage(c0, (c0 & 1) ? tbuf1 : tbuf0);

    float acc = 0.0f;

    for (int m = c0; m < c1; m++) {
        if (m + 1 < c1) {
            stage(m + 1, ((m + 1) & 1) ? tbuf1 : tbuf0);
            cp_wait<1>();
        } else {
            cp_wait<0>();
        }
        __syncthreads();

        const int R  = m * CH;
        const int nr = min(R + CH, 513) - R;

        // Exact owned j-window: iy in [R-1, R+nr-1), j in [0,512).
        int jlo = first_j_ge((float)(R - 1),      iyS, cy, invcy);
        int jhi = first_j_ge((float)(R + nr - 1), iyS, cy, invcy);
        jlo = max(jlo, 0);
        jhi = min(jhi, 512);
        const int len = jhi - jlo;

        // Local coords: iyl = iy - (R-1) in [0, nr+1); tile row = floor(iyl).
        float iyl    = fmaf((float)jlo, cy,  iyS) - (float)(R - 1);
        float ix_loc = fmaf((float)jlo, dxj, ixS) + 2.0f;

        const __half2* __restrict__ tb = (m & 1) ? tbuf1 : tbuf0;

        #pragma unroll 4
        for (int k = 0; k < len; k++) {
            int yi = __float2int_rd(iyl);
            yi = min(max(yi, 0), nr - 1);              // insurance vs ulp drift
            const float wy = iyl - (float)yi;
            const int   si0 = __float2int_rd(ix_loc);
            const float wx  = ix_loc - (float)si0;
            const int   si  = min(max(si0, 0), 514);   // exact via zero guard cols
            const __half2 wx2 = __float2half2_rn(wx);
            const __half2* p = tb + yi * TST + si;
            const __half2 A = p[0];                    // (v00, v10)
            const __half2 B = p[1];                    // (v01, v11)
            const __half2 mm = __hfma2(wx2, __hsub2(B, A), A);
            const float top = __low2float(mm);
            const float bot = __high2float(mm);
            acc += fmaf(wy, bot - top, top);
            iyl    += cy;
            ix_loc += dxj;
        }
        __syncthreads();
    }
    atomicAdd(&g_sino[a * WW + w], acc);
}

// ---------------------------------------------------------------------------
// Kernel 3: fused MSE + TV reduction + finalize (last block writes out).
// ---------------------------------------------------------------------------
__global__ void loss_kernel(const float* __restrict__ pred,
                            const float* __restrict__ sino_tgt,
                            float* __restrict__ out) {
    const int tid    = blockIdx.x * blockDim.x + threadIdx.x;
    const int stride = gridDim.x * blockDim.x;

    float lp = 0.0f;
    for (int i = tid; i < AA * WW; i += stride) {
        const float df = g_sino[i] - sino_tgt[i];
        lp = fmaf(df, df, lp);
    }

    float lt = 0.0f;
    const int TVW = WW - 1, TVH = HH - 1;
    for (int i = tid; i < TVH * TVW; i += stride) {
        const int y = i / TVW;
        const int x = i - y * TVW;
        const float p  = pred[y * WW + x];
        const float dx = pred[y * WW + x + 1] - p;
        const float dy = pred[(y + 1) * WW + x] - p;
        lt += sqrtf(fmaf(dx, dx, fmaf(dy, dy, 1e-8f)));
    }

    for (int off = 16; off > 0; off >>= 1) {
        lp += __shfl_down_sync(0xFFFFFFFFu, lp, off);
        lt += __shfl_down_sync(0xFFFFFFFFu, lt, off);
    }
    __shared__ float s_lp[32], s_lt[32];
    const int lane = threadIdx.x & 31;
    const int warp = threadIdx.x >> 5;
    if (lane == 0) { s_lp[warp] = lp; s_lt[warp] = lt; }
    __syncthreads();
    const int nwarps = blockDim.x >> 5;
    if (warp == 0) {
        lp = (lane < nwarps) ? s_lp[lane] : 0.0f;
        lt = (lane < nwarps) ? s_lt[lane] : 0.0f;
        for (int off = 16; off > 0; off >>= 1) {
            lp += __shfl_down_sync(0xFFFFFFFFu, lp, off);
            lt += __shfl_down_sync(0xFFFFFFFFu, lt, off);
        }
        if (lane == 0) {
            atomicAdd(&g_acc[0], (double)lp);
            atomicAdd(&g_acc[1], (double)lt);
            __threadfence();
            const unsigned done = atomicAdd(&g_cnt, 1u);
            if (done == gridDim.x - 1) {
                __threadfence();
                const double loss_proj = g_acc[0] / (double)(AA * WW);
                const double loss_tv   = g_acc[1] / (double)((HH - 1) * (WW - 1));
                out[0] = (float)(loss_proj + 0.01 * loss_tv);
            }
        }
    }
}

// ---------------------------------------------------------------------------
extern "C" void kernel_launch(void* const* d_in, const int* in_sizes, int n_in,
                              void* d_out, int out_size) {
    const float* pred     = (const float*)d_in[0];   // [1,512,512]
    const float* sinogram = (const float*)d_in[1];   // [1,180,512]
    const float* angles   = (const float*)d_in[2];   // [180]
    float* out = (float*)d_out;

    cudaFuncSetAttribute(radon_kernel,
                         cudaFuncAttributeMaxDynamicSharedMemorySize, DYN_SMEM);

    prep_normal<<<513, 544>>>(pred);

    dim3 tgrid(17, 17);
    prep_transpose<<<tgrid, dim3(32, 8)>>>(pred);

    dim3 rgrid(AA, NSPLIT);                          // 180 x 10 = 1800 blocks
    radon_kernel<<<rgrid, 512, DYN_SMEM>>>(angles);

    loss_kernel<<<592, 256>>>(pred, sinogram, out);
}

// round 10
// speedup vs baseline: 1.2414x; 1.0298x over previous
#include <cuda_runtime.h>
#include <cuda_fp16.h>
#include <math.h>

#define HH 512
#define WW 512
#define AA 180
#define TST 516             // pair-image row stride in half2 (2064 B/row)
#define ROWB (TST * 4)      // tile row stride in bytes
#define CH 16               // padded top-rows per chunk
#define NCHUNK 33           // ceil(513 / 16)
#define NSPLIT 10           // chunk-groups per angle -> 1800 blocks
#define TILE_H2 (CH * TST)  // 8256 half2 = 33,024 B per buffer
#define DYN_SMEM (2 * TILE_H2 * 4)   // 66,048 B

// Vertical-pair images: g_V[y*TST+s] = half2(P(y,s-1), P(y+1,s-1)),
// P(r,c) = pred[r-1][c-1] inside [1,512]^2 else 0. Cols s=0,1,514,515 are zero.
__device__ __align__(16) __half2 g_V[513 * TST];
__device__ __align__(16) __half2 g_VT[513 * TST];   // transposed orientation
__device__ __align__(16) float g_sino[AA * WW];
__device__ double g_acc[2];
__device__ unsigned g_cnt;

// ---------------- cp.async helpers ----------------
__device__ __forceinline__ void cp_async16(void* smem, const void* gmem) {
    unsigned s = (unsigned)__cvta_generic_to_shared(smem);
    asm volatile("cp.async.cg.shared.global [%0], [%1], 16;\n" :: "r"(s), "l"(gmem));
}
__device__ __forceinline__ void cp_commit() {
    asm volatile("cp.async.commit_group;\n");
}
template <int N> __device__ __forceinline__ void cp_wait() {
    asm volatile("cp.async.wait_group %0;\n" :: "n"(N));
}

// ---------------------------------------------------------------------------
// Kernel 1a: normal vertical-pair image (coalesced) + zero accumulators.
// ---------------------------------------------------------------------------
__global__ void prep_normal(const float* __restrict__ pred) {
    const int y = blockIdx.x;          // 0..512
    const int s = threadIdx.x;         // 0..543
    if (s < TST) {
        float a = 0.0f, b = 0.0f;
        if (s >= 2 && s <= 513) {
            const int pc = s - 2;
            if (y >= 1 && y <= 512) a = pred[(y - 1) * 512 + pc];
            if (y <= 511)           b = pred[y * 512 + pc];
        }
        g_V[y * TST + s] = __floats2half2_rn(a, b);
    }
    const int gid = blockIdx.x * blockDim.x + threadIdx.x;
    if (gid < AA * WW) g_sino[gid] = 0.0f;
    if (gid == 0) { g_acc[0] = 0.0; g_acc[1] = 0.0; g_cnt = 0u; }
}

// ---------------------------------------------------------------------------
// Kernel 1b: transposed vertical-pair image via SMEM tile.
// ---------------------------------------------------------------------------
__global__ void prep_transpose(const float* __restrict__ pred) {
    __shared__ float t[32][35];
    const int s0 = blockIdx.x * 32;
    const int y0 = blockIdx.y * 32;
    const int tx = threadIdx.x;
    const int ty = threadIdx.y;

    for (int i = ty; i < 32; i += 8) {
        const int pr = s0 - 2 + i;
        {
            const int pc = y0 - 1 + tx;
            t[i][tx] = ((unsigned)pr < 512u && (unsigned)pc < 512u)
                       ? pred[pr * 512 + pc] : 0.0f;
        }
        if (tx < 2) {
            const int pc = y0 + 31 + tx;
            t[i][32 + tx] = ((unsigned)pr < 512u && (unsigned)pc < 512u)
                            ? pred[pr * 512 + pc] : 0.0f;
        }
    }
    __syncthreads();

    for (int j = ty; j < 32; j += 8) {
        const int y = y0 + j;
        const int s = s0 + tx;
        if (y < 513 && s < TST)
            g_VT[y * TST + s] = __floats2half2_rn(t[tx][j], t[tx][j + 1]);
    }
}

// ---------------------------------------------------------------------------
// Exact first-j with iy(j) >= bound (ceilf estimate corrected +-1 against the
// same fmaf formula -> adjacent chunks compute bitwise-identical boundaries).
// ---------------------------------------------------------------------------
__device__ __forceinline__ int first_j_ge(float bound, float iyS, float cy, float invcy) {
    int j = (int)ceilf((bound - iyS) * invcy);
    if (fmaf((float)(j - 1), cy, iyS) >= bound) j -= 1;
    if (fmaf((float)j, cy, iyS) < bound)        j += 1;
    return j;
}

// ---------------------------------------------------------------------------
// Incremental DDA chunk accumulation. XPOS selects the x-step sign variant.
// wy/wx wrap predicates replace per-trip floor chains; clamps are single
// unsigned-min ops (si<0 wraps to huge -> 514 -> zero guard pair, exact).
// ---------------------------------------------------------------------------
template <bool XPOS>
__device__ __forceinline__ float chunk_accum(const __half2* __restrict__ tb,
                                             int len, int nr,
                                             float iyl0, float ix0,
                                             float cy, float dxj) {
    int yi0 = __float2int_rd(iyl0);
    yi0 = min(max(yi0, 0), nr - 1);
    float wy = iyl0 - (float)yi0;
    int rowoff = yi0 * ROWB;
    const unsigned rowcap = (unsigned)((nr - 1) * ROWB);

    int si = __float2int_rd(ix0);
    float wx = ix0 - (float)si;

    const char* __restrict__ base = (const char*)tb;
    float acc = 0.0f;

    #pragma unroll 4
    for (int k = 0; k < len; k++) {
        const unsigned sic = min((unsigned)si, 514u);
        const unsigned roc = min((unsigned)rowoff, rowcap);
        const __half2* p = (const __half2*)(base + roc + sic * 4u);
        const __half2 A = p[0];                    // (v00, v10)
        const __half2 B = p[1];                    // (v01, v11)
        const __half2 wx2 = __float2half2_rn(wx);
        const __half2 mm = __hfma2(wx2, __hsub2(B, A), A);
        const float top = __low2float(mm);
        const float bot = __high2float(mm);
        acc += fmaf(wy, bot - top, top);

        wy += cy;
        if (wy >= 1.0f) { wy -= 1.0f; rowoff += ROWB; }
        if (XPOS) {
            wx += dxj;
            if (wx >= 1.0f) { wx -= 1.0f; si += 1; }
        } else {
            wx += dxj;
            if (wx < 0.0f)  { wx += 1.0f; si -= 1; }
        }
    }
    return acc;
}

// ---------------------------------------------------------------------------
// Kernel 2: radon with exact guardless j-windows + incremental DDA body.
// ---------------------------------------------------------------------------
__global__ __launch_bounds__(512, 3) void radon_kernel(const float* __restrict__ angles) {
    extern __shared__ __align__(16) unsigned char dynsmem[];
    __half2* const tbuf0 = (__half2*)dynsmem;
    __half2* const tbuf1 = tbuf0 + TILE_H2;

    const int a = blockIdx.x;
    const int w = threadIdx.x;

    const float ang = angles[a];
    const float sn = sinf(ang);
    const float cs = cosf(ang);
    const bool  swp = fabsf(sn) > fabsf(cs);

    const float c = swp ? -sn : cs;                    // |c| >= 0.7071
    const float d = swp ?  cs : -sn;
    const float u = (float)w + 0.5f - 256.0f;
    const float by = fmaf(swp ? cs : sn, u, 255.5f);
    const float bx = fmaf(swp ? sn : cs, u, 255.5f);
    const __half2* __restrict__ img = swp ? g_VT : g_V;

    const float sgn   = (c >= 0.0f) ? 1.0f : -1.0f;
    const float cy    = fabsf(c);
    const float invcy = 1.0f / cy;
    const float iyS   = fmaf(-255.5f, cy, by);         // iy at j=0, increasing
    const float dxj   = sgn * d;
    const float ixS   = fmaf(-sgn * 255.5f, d, bx);
    const bool  xpos  = (dxj >= 0.0f);                 // block-uniform

    const int c0 = (NCHUNK * blockIdx.y) / NSPLIT;
    const int c1 = (NCHUNK * (blockIdx.y + 1)) / NSPLIT;

    auto stage = [&](int m, __half2* dstbuf) {
        const int R  = m * CH;
        const int nr = min(R + CH, 513) - R;
        const int n16 = nr * (TST / 4);
        const float4* __restrict__ src = (const float4*)(img + R * TST);
        float4* dst = (float4*)dstbuf;
        for (int t = threadIdx.x; t < n16; t += 512)
            cp_async16(&dst[t], &src[t]);
        cp_commit();
    };

    stage(c0, (c0 & 1) ? tbuf1 : tbuf0);

    float acc = 0.0f;

    for (int m = c0; m < c1; m++) {
        if (m + 1 < c1) {
            stage(m + 1, ((m + 1) & 1) ? tbuf1 : tbuf0);
            cp_wait<1>();
        } else {
            cp_wait<0>();
        }
        __syncthreads();

        const int R  = m * CH;
        const int nr = min(R + CH, 513) - R;

        // Exact owned j-window: iy in [R-1, R+nr-1), j in [0,512).
        int jlo = first_j_ge((float)(R - 1),      iyS, cy, invcy);
        int jhi = first_j_ge((float)(R + nr - 1), iyS, cy, invcy);
        jlo = max(jlo, 0);
        jhi = min(jhi, 512);
        const int len = jhi - jlo;

        const float iyl0 = fmaf((float)jlo, cy,  iyS) - (float)(R - 1);
        const float ix0  = fmaf((float)jlo, dxj, ixS) + 2.0f;

        const __half2* __restrict__ tb = (m & 1) ? tbuf1 : tbuf0;

        if (xpos) acc += chunk_accum<true >(tb, len, nr, iyl0, ix0, cy, dxj);
        else      acc += chunk_accum<false>(tb, len, nr, iyl0, ix0, cy, dxj);

        __syncthreads();
    }
    atomicAdd(&g_sino[a * WW + w], acc);
}

// ---------------------------------------------------------------------------
// Kernel 3: fused MSE + TV reduction + finalize (last block writes out).
// ---------------------------------------------------------------------------
__global__ void loss_kernel(const float* __restrict__ pred,
                            const float* __restrict__ sino_tgt,
                            float* __restrict__ out) {
    const int tid    = blockIdx.x * blockDim.x + threadIdx.x;
    const int stride = gridDim.x * blockDim.x;

    float lp = 0.0f;
    for (int i = tid; i < AA * WW; i += stride) {
        const float df = g_sino[i] - sino_tgt[i];
        lp = fmaf(df, df, lp);
    }

    float lt = 0.0f;
    const int TVW = WW - 1, TVH = HH - 1;
    for (int i = tid; i < TVH * TVW; i += stride) {
        const int y = i / TVW;
        const int x = i - y * TVW;
        const float p  = pred[y * WW + x];
        const float dx = pred[y * WW + x + 1] - p;
        const float dy = pred[(y + 1) * WW + x] - p;
        lt += sqrtf(fmaf(dx, dx, fmaf(dy, dy, 1e-8f)));
    }

    for (int off = 16; off > 0; off >>= 1) {
        lp += __shfl_down_sync(0xFFFFFFFFu, lp, off);
        lt += __shfl_down_sync(0xFFFFFFFFu, lt, off);
    }
    __shared__ float s_lp[32], s_lt[32];
    const int lane = threadIdx.x & 31;
    const int warp = threadIdx.x >> 5;
    if (lane == 0) { s_lp[warp] = lp; s_lt[warp] = lt; }
    __syncthreads();
    const int nwarps = blockDim.x >> 5;
    if (warp == 0) {
        lp = (lane < nwarps) ? s_lp[lane] : 0.0f;
        lt = (lane < nwarps) ? s_lt[lane] : 0.0f;
        for (int off = 16; off > 0; off >>= 1) {
            lp += __shfl_down_sync(0xFFFFFFFFu, lp, off);
            lt += __shfl_down_sync(0xFFFFFFFFu, lt, off);
        }
        if (lane == 0) {
            atomicAdd(&g_acc[0], (double)lp);
            atomicAdd(&g_acc[1], (double)lt);
            __threadfence();
            const unsigned done = atomicAdd(&g_cnt, 1u);
            if (done == gridDim.x - 1) {
                __threadfence();
                const double loss_proj = g_acc[0] / (double)(AA * WW);
                const double loss_tv   = g_acc[1] / (double)((HH - 1) * (WW - 1));
                out[0] = (float)(loss_proj + 0.01 * loss_tv);
            }
        }
    }
}

// ---------------------------------------------------------------------------
extern "C" void kernel_launch(void* const* d_in, const int* in_sizes, int n_in,
                              void* d_out, int out_size) {
    const float* pred     = (const float*)d_in[0];   // [1,512,512]
    const float* sinogram = (const float*)d_in[1];   // [1,180,512]
    const float* angles   = (const float*)d_in[2];   // [180]
    float* out = (float*)d_out;

    cudaFuncSetAttribute(radon_kernel,
                         cudaFuncAttributeMaxDynamicSharedMemorySize, DYN_SMEM);

    prep_normal<<<513, 544>>>(pred);

    dim3 tgrid(17, 17);
    prep_transpose<<<tgrid, dim3(32, 8)>>>(pred);

    dim3 rgrid(AA, NSPLIT);                          // 180 x 10 = 1800 blocks
    radon_kernel<<<rgrid, 512, DYN_SMEM>>>(angles);

    loss_kernel<<<592, 256>>>(pred, sinogram, out);
}